// round 17
// baseline (speedup 1.0000x reference)
#include <cuda_runtime.h>
#include <cuda_fp16.h>
#include <cstdint>
#include <stdint.h>
#include <math.h>

#define Bz 8
#define Tz 4096
#define Cz 768
#define Hz 64

// global scratch (allocation-free rule)
__device__ __half g_q16[Bz * Tz * Hz];
__device__ __half g_k16[Bz * Tz * Hz];
__device__ __half g_v16[Bz * Tz * Hz];
__device__ __half g_wth[3 * Hz * Cz];
__device__ __half g_wtl[3 * Hz * Cz];
// split-K partials: [part][b][t][h] and [part][b][t]
__device__ float g_po[2 * Bz * Tz * Hz];
__device__ float g_pm[2 * Bz * Tz];
__device__ float g_pl[2 * Bz * Tz];

// ---------------------------------------------------------------------------
// helpers
// ---------------------------------------------------------------------------
__device__ __forceinline__ uint32_t smem_u32(const void* p) {
    uint32_t a;
    asm("{ .reg .u64 t; cvta.to.shared.u64 t, %1; cvt.u32.u64 %0, t; }"
        : "=r"(a) : "l"(p));
    return a;
}
__device__ __forceinline__ void ldsm4(uint32_t* r, uint32_t a) {
    asm volatile("ldmatrix.sync.aligned.m8n8.x4.shared.b16 {%0,%1,%2,%3}, [%4];"
        : "=r"(r[0]), "=r"(r[1]), "=r"(r[2]), "=r"(r[3]) : "r"(a));
}
__device__ __forceinline__ void ldsm4t(uint32_t* r, uint32_t a) {
    asm volatile("ldmatrix.sync.aligned.m8n8.x4.trans.shared.b16 {%0,%1,%2,%3}, [%4];"
        : "=r"(r[0]), "=r"(r[1]), "=r"(r[2]), "=r"(r[3]) : "r"(a));
}
__device__ __forceinline__ void mma16816(float* d, const uint32_t* a,
                                         const uint32_t* b) {
    asm volatile(
        "mma.sync.aligned.m16n8k16.row.col.f32.f16.f16.f32 "
        "{%0,%1,%2,%3}, {%4,%5,%6,%7}, {%8,%9}, {%0,%1,%2,%3};"
        : "+f"(d[0]), "+f"(d[1]), "+f"(d[2]), "+f"(d[3])
        : "r"(a[0]), "r"(a[1]), "r"(a[2]), "r"(a[3]), "r"(b[0]), "r"(b[1]));
}
__device__ __forceinline__ void cp16(uint32_t dst, const void* src) {
    asm volatile("cp.async.cg.shared.global [%0], [%1], 16;"
                 :: "r"(dst), "l"(src) : "memory");
}
__device__ __forceinline__ void cpcommit() {
    asm volatile("cp.async.commit_group;" ::: "memory");
}
template <int N> __device__ __forceinline__ void cpwait() {
    asm volatile("cp.async.wait_group %0;" :: "n"(N) : "memory");
}
__device__ __forceinline__ float ex2(float x) {
    float y;
    asm("ex2.approx.f32 %0, %1;" : "=f"(y) : "f"(x));
    return y;
}
__device__ __forceinline__ uint32_t packh2(float a, float b) {
    __half2 h = __floats2half2_rn(a, b);
    return reinterpret_cast<uint32_t&>(h);
}
__device__ __forceinline__ void splith(float v, __half& hi, __half& lo) {
    hi = __float2half(v);
    lo = __float2half(v - __half2float(hi));
}

// log2(e) folded into the attention scale: 768^-0.5 * log2(e)
#define QSCALE 0.052057446116f

// ---------------------------------------------------------------------------
// prep: W -> W^T fp16 hi/lo via smem transpose, coalesced both ways.
// grid(36): mat = bx/12, c-tile = bx%12 (64 c each).
// ---------------------------------------------------------------------------
__global__ void prep_kernel(const float* __restrict__ Wk,
                            const float* __restrict__ Wq,
                            const float* __restrict__ Wv) {
    __shared__ float ts[64][65];
    int mat = blockIdx.x / 12;
    int c0 = (blockIdx.x % 12) * 64;
    const float* W = (mat == 0) ? Wq : ((mat == 1) ? Wk : Wv);
    int tid = threadIdx.x;
    // load 64 c-rows x 64 h-cols, coalesced
    for (int i = tid; i < 4096; i += 256) {
        int r = i >> 6, h = i & 63;
        ts[r][h] = W[(long)(c0 + r) * Hz + h];
    }
    __syncthreads();
    // write transposed [h][c], coalesced
    for (int i = tid; i < 4096; i += 256) {
        int h = i >> 6, cc = i & 63;
        __half hi, lo;
        splith(ts[cc][h], hi, lo);
        long o = (long)mat * Hz * Cz + (long)h * Cz + c0 + cc;
        g_wth[o] = hi;
        g_wtl[o] = lo;
    }
}

// ---------------------------------------------------------------------------
// projection: all 3 mats per block; 2-term fp16 (x single, W hi/lo).
// W fragments via ldsm4 np-pairing.
// ---------------------------------------------------------------------------
#define PLD 72
#define PX 0
#define PW 18432
#define PSMEM (18432 + 3 * 18432)

__global__ void __launch_bounds__(256) proj_kernel(const float* __restrict__ x) {
    extern __shared__ char smem[];
    uint32_t sb = smem_u32(smem);

    long row0 = (long)blockIdx.x * 128;
    int tid = threadIdx.x, wid = tid / 32, lane = tid % 32;
    int wr0 = wid * 16;
    int rr = lane % 8, grp = lane / 8;

    float acc[3][8][4] = {};

    for (int it = 0; it < 12; it++) {
        int k0 = it * 64;
        __syncthreads();
        for (int i = tid; i < 128 * 8; i += 256) {
            int r = i / 8, ch = i % 8;
            const float* src = &x[(row0 + r) * Cz + k0 + ch * 8];
            float4 a = *(const float4*)src;
            float4 b = *(const float4*)(src + 4);
            uint4 v;
            v.x = packh2(a.x, a.y);
            v.y = packh2(a.z, a.w);
            v.z = packh2(b.x, b.y);
            v.w = packh2(b.z, b.w);
            *(uint4*)(smem + PX + (uint32_t)(r * PLD + ch * 8) * 2) = v;
        }
        for (int i = tid; i < 3 * 64 * 8; i += 256) {
            int mat = i / 512, rem = i % 512;
            int h = rem / 8, ch = rem % 8;
            uint32_t off = PW + mat * 18432 + (uint32_t)(h * PLD + ch * 8) * 2;
            *(uint4*)(smem + off) =
                *(const uint4*)(g_wth + mat * Hz * Cz + h * Cz + k0 + ch * 8);
            *(uint4*)(smem + off + 9216) =
                *(const uint4*)(g_wtl + mat * Hz * Cz + h * Cz + k0 + ch * 8);
        }
        __syncthreads();

        #pragma unroll
        for (int kc = 0; kc < 4; kc++) {
            uint32_t xa[4];
            uint32_t aoff = (uint32_t)((wr0 + rr + (grp & 1) * 8) * PLD
                                       + kc * 16 + (grp >> 1) * 8) * 2;
            ldsm4(xa, sb + PX + aoff);
            #pragma unroll
            for (int mat = 0; mat < 3; mat++) {
                uint32_t wb = sb + PW + (uint32_t)mat * 18432;
                #pragma unroll
                for (int np = 0; np < 4; np++) {
                    uint32_t row = (uint32_t)(np * 16 + ((grp >> 1) ? 8 : 0) + rr);
                    uint32_t col = (uint32_t)(kc * 16 + (grp & 1) * 8);
                    uint32_t off = (row * PLD + col) * 2;
                    uint32_t bh[4], bl[4];
                    ldsm4(bh, wb + off);
                    ldsm4(bl, wb + 9216 + off);
                    mma16816(acc[mat][np * 2], xa, bh);
                    mma16816(acc[mat][np * 2], xa, bl);
                    mma16816(acc[mat][np * 2 + 1], xa, bh + 2);
                    mma16816(acc[mat][np * 2 + 1], xa, bl + 2);
                }
            }
        }
    }

    long rA = row0 + wr0 + lane / 4;
    long rB = rA + 8;
    int cb = 2 * (lane % 4);
    #pragma unroll
    for (int mat = 0; mat < 3; mat++) {
        __half* outp = (mat == 0) ? g_q16 : ((mat == 1) ? g_k16 : g_v16);
        float scale = (mat == 0) ? QSCALE : 1.0f;
        #pragma unroll
        for (int n = 0; n < 8; n++) {
            *(uint32_t*)&outp[rA * Hz + n * 8 + cb] =
                packh2(acc[mat][n][0] * scale, acc[mat][n][1] * scale);
            *(uint32_t*)&outp[rB * Hz + n * 8 + cb] =
                packh2(acc[mat][n][2] * scale, acc[mat][n][3] * scale);
        }
    }
}

// ---------------------------------------------------------------------------
// flash attention, cross-block split-K, l via ones-column mma.
// grid (512): g -> qt = 31-(g>>4) (globally longest-first), part, b.
// ---------------------------------------------------------------------------
#define LDA 72
#define QS 0
#define ST0 18432
#define STG 36864
#define ASMEM (18432 + 2 * 36864)   // 92160

__global__ void __launch_bounds__(256, 2) attn_kernel() {
    extern __shared__ char smem[];
    uint32_t sb = smem_u32(smem);

    int tid = threadIdx.x, wid = tid / 32, lane = tid % 32;
    int g = (int)blockIdx.x;
    int qt = 31 - (g >> 4);
    int rem = g & 15;
    int part = rem >> 3;
    int b = rem & 7;
    int q0 = qt * 128;
    int rr = lane % 8, grp = lane / 8;
    int wr0 = wid * 16;
    int r0a = q0 + wr0;

    int njt = qt + 1;
    int nj0 = (njt + 1) >> 1;
    int lo = part ? nj0 : 0;
    int hi = part ? njt : nj0;

    const __half* gq = g_q16 + ((long)b * Tz + q0) * Hz;
    const __half* gk = g_k16 + (long)b * Tz * Hz;
    const __half* gv = g_v16 + (long)b * Tz * Hz;

    float O[8][4] = {};
    float Ol[4] = {};
    float mrow[2] = {-1e30f, -1e30f};

    const uint32_t vo[2] = {0x3C003C00u, 0x3C003C00u};   // fp16 ones fragment

    if (lo < hi) {
        // ---- stage Q (128 rows fp16) ----
        for (int i = tid; i < 1024; i += 256) {
            int r = i >> 3, ch = i & 7;
            *(uint4*)(smem + QS + (uint32_t)(r * LDA + ch * 8) * 2) =
                *(const uint4*)(gq + r * Hz + ch * 8);
        }
        __syncthreads();

        uint32_t qf[4][4];
        #pragma unroll
        for (int kc = 0; kc < 4; kc++) {
            uint32_t aoff = (uint32_t)((wr0 + rr + (grp & 1) * 8) * LDA
                                       + kc * 16 + (grp >> 1) * 8) * 2;
            ldsm4(qf[kc], sb + QS + aoff);
        }

        // prologue: stage tile lo
        for (int i = tid; i < 2048; i += 256) {
            int arr = i >> 10, idx = i & 1023;
            int r = idx >> 3, ch = idx & 7;
            const __half* src = arr ? gv : gk;
            cp16(sb + ST0 + arr * 18432 + (uint32_t)(r * LDA + ch * 8) * 2,
                 src + (long)(lo * 128 + r) * Hz + ch * 8);
        }
        cpcommit();

        for (int j = lo; j < hi; j++) {
            uint32_t bufc = sb + ST0 + (uint32_t)((j - lo) & 1) * STG;
            if (j + 1 < hi) {
                uint32_t bufn = sb + ST0 + (uint32_t)((j + 1 - lo) & 1) * STG;
                int jb = (j + 1) * 128;
                for (int i = tid; i < 2048; i += 256) {
                    int arr = i >> 10, idx = i & 1023;
                    int r = idx >> 3, ch = idx & 7;
                    const __half* src = arr ? gv : gk;
                    cp16(bufn + arr * 18432 + (uint32_t)(r * LDA + ch * 8) * 2,
                         src + (long)(jb + r) * Hz + ch * 8);
                }
                cpcommit();
                cpwait<1>();
            } else {
                cpwait<0>();
            }
            __syncthreads();

            #pragma unroll
            for (int half = 0; half < 2; half++) {
                int kb = j * 128 + half * 64;
                if (kb > r0a + 15) break;
                uint32_t rbase = (uint32_t)(half * 64);

                // ---- S = Q K^T ----
                float S[8][4] = {};
                #pragma unroll
                for (int np = 0; np < 4; np++) {
                    #pragma unroll
                    for (int kc = 0; kc < 4; kc++) {
                        uint32_t row = rbase + (uint32_t)(np * 16 + ((grp >> 1) ? 8 : 0) + rr);
                        uint32_t col = (uint32_t)(kc * 16 + (grp & 1) * 8);
                        uint32_t bh[4];
                        ldsm4(bh, bufc + (row * LDA + col) * 2);
                        mma16816(S[np * 2], qf[kc], bh);
                        mma16816(S[np * 2 + 1], qf[kc], bh + 2);
                    }
                }

                // ---- causal mask ----
                int rA = r0a + lane / 4;
                int rB = rA + 8;
                if (kb + 63 > r0a) {
                    #pragma unroll
                    for (int n = 0; n < 8; n++) {
                        int c0 = kb + n * 8 + 2 * (lane % 4);
                        if (c0 > rA)     S[n][0] = -1e30f;
                        if (c0 + 1 > rA) S[n][1] = -1e30f;
                        if (c0 > rB)     S[n][2] = -1e30f;
                        if (c0 + 1 > rB) S[n][3] = -1e30f;
                    }
                }

                // ---- online max (exp2 domain); l handled by ones-mma ----
                float mA = -1e30f, mB = -1e30f;
                #pragma unroll
                for (int n = 0; n < 8; n++) {
                    mA = fmaxf(mA, fmaxf(S[n][0], S[n][1]));
                    mB = fmaxf(mB, fmaxf(S[n][2], S[n][3]));
                }
                #pragma unroll
                for (int off = 1; off < 4; off <<= 1) {
                    mA = fmaxf(mA, __shfl_xor_sync(0xffffffffu, mA, off));
                    mB = fmaxf(mB, __shfl_xor_sync(0xffffffffu, mB, off));
                }
                float mnA = fmaxf(mrow[0], mA), mnB = fmaxf(mrow[1], mB);
                float aA = ex2(mrow[0] - mnA), aB = ex2(mrow[1] - mnB);
                mrow[0] = mnA; mrow[1] = mnB;
                #pragma unroll
                for (int n = 0; n < 8; n++) {
                    S[n][0] = ex2(S[n][0] - mnA);
                    S[n][1] = ex2(S[n][1] - mnA);
                    S[n][2] = ex2(S[n][2] - mnB);
                    S[n][3] = ex2(S[n][3] - mnB);
                }
                #pragma unroll
                for (int n = 0; n < 8; n++) {
                    O[n][0] *= aA; O[n][1] *= aA; O[n][2] *= aB; O[n][3] *= aB;
                }
                Ol[0] *= aA; Ol[1] *= aA; Ol[2] *= aB; Ol[3] *= aB;

                // ---- O += P V ; l += P @ ones ----
                #pragma unroll
                for (int kc = 0; kc < 4; kc++) {
                    int t0 = 2 * kc, t1 = 2 * kc + 1;
                    uint32_t ph[4];
                    ph[0] = packh2(S[t0][0], S[t0][1]);
                    ph[1] = packh2(S[t0][2], S[t0][3]);
                    ph[2] = packh2(S[t1][0], S[t1][1]);
                    ph[3] = packh2(S[t1][2], S[t1][3]);
                    mma16816(Ol, ph, vo);
                    #pragma unroll
                    for (int np = 0; np < 4; np++) {
                        uint32_t row = rbase + (uint32_t)(kc * 16 + ((grp & 1) ? 8 : 0) + rr);
                        uint32_t col = (uint32_t)(np * 16 + (grp >> 1) * 8);
                        uint32_t vh[4];
                        ldsm4t(vh, bufc + 18432 + (row * LDA + col) * 2);
                        mma16816(O[np * 2], ph, vh);
                        mma16816(O[np * 2 + 1], ph, vh + 2);
                    }
                }
            }
            __syncthreads();
        }
    }

    // ---- write partial (unnormalized O, m, l) ----
    long prow = ((long)(part * Bz + b)) * Tz + r0a + lane / 4;
    long prB = prow + 8;
    int cb = 2 * (lane % 4);
    #pragma unroll
    for (int n = 0; n < 8; n++) {
        *(float2*)&g_po[prow * Hz + n * 8 + cb] = make_float2(O[n][0], O[n][1]);
        *(float2*)&g_po[prB * Hz + n * 8 + cb] = make_float2(O[n][2], O[n][3]);
    }
    if ((lane & 3) == 0) {
        g_pm[prow] = mrow[0];
        g_pm[prB]  = mrow[1];
        g_pl[prow] = Ol[0];
        g_pl[prB]  = Ol[2];
    }
}

// ---------------------------------------------------------------------------
// combine: merge the two split-K partials.
// ---------------------------------------------------------------------------
__global__ void combine_kernel(float* __restrict__ out) {
    int idx = blockIdx.x * 256 + threadIdx.x;
    int c4 = (idx & 15) * 4;
    long row = idx >> 4;
    float m0 = g_pm[row], m1 = g_pm[Bz * Tz + row];
    float l0 = g_pl[row], l1 = g_pl[Bz * Tz + row];
    float ms = fmaxf(m0, m1);
    float a0 = ex2(m0 - ms), a1 = ex2(m1 - ms);
    float inv = 1.0f / (l0 * a0 + l1 * a1);
    float4 o0 = *(const float4*)&g_po[row * Hz + c4];
    float4 o1 = *(const float4*)&g_po[(long)Bz * Tz * Hz + row * Hz + c4];
    float4 r;
    r.x = (o0.x * a0 + o1.x * a1) * inv;
    r.y = (o0.y * a0 + o1.y * a1) * inv;
    r.z = (o0.z * a0 + o1.z * a1) * inv;
    r.w = (o0.w * a0 + o1.w * a1) * inv;
    *(float4*)&out[row * Hz + c4] = r;
}

extern "C" void kernel_launch(void* const* d_in, const int* in_sizes, int n_in,
                              void* d_out, int out_size) {
    const float* x  = (const float*)d_in[0];
    const float* Wk = (const float*)d_in[1];
    const float* Wq = (const float*)d_in[2];
    const float* Wv = (const float*)d_in[3];
    float* out = (float*)d_out;

    prep_kernel<<<36, 256>>>(Wk, Wq, Wv);

    cudaFuncSetAttribute(proj_kernel,
                         cudaFuncAttributeMaxDynamicSharedMemorySize, PSMEM);
    proj_kernel<<<(Bz * Tz) / 128, 256, PSMEM>>>(x);

    cudaFuncSetAttribute(attn_kernel,
                         cudaFuncAttributeMaxDynamicSharedMemorySize, ASMEM);
    attn_kernel<<<512, 256, ASMEM>>>();

    combine_kernel<<<2048, 256>>>(out);
}